// round 7
// baseline (speedup 1.0000x reference)
#include <cuda_runtime.h>
#include <cuda_bf16.h>
#include <math.h>
#include <stdint.h>

// ---------------- constants ----------------
#define BATCH 4096
#define NR 512
#define RI 4096
#define OD 64
#define OUT_V_OFF 0
#define OUT_REC_OFF 262144
#define OUT_MASK_OFF 524288

// conv-kernel SMEM layout (bytes)
#define XROW 264                  // bf16 elems per padded-pos row (256 ic + 8 pad)
#define XT_HI 0                   // 160 * 264 * 2 = 84480
#define XT_LO 84480
#define BBUF  168960              // 2 buffers * (hi 9216 + lo 9216)
#define BPLANE 9216               // 64 rows * 144B
#define BBUFSZ 18432
#define CONV_SMEM 205824

// ---------------- scratch (device globals) ----------------
__device__ __nv_bfloat16 g_wB_hi[2304 * 64];   // [k = j*256+ic][oc]
__device__ __nv_bfloat16 g_wB_lo[2304 * 64];
__device__ float g_u[(size_t)BATCH * RI];
__device__ float g_WcT[RI * OD];
__device__ float g_bij[NR * 2];
__device__ float g_c[NR * 2];
__device__ float g_s[BATCH * OD];
__device__ float g_v[BATCH * OD];
__device__ float g_G[RI * OD];
__device__ float g_r[BATCH * 64];              // dec3 split-K accumulator
__device__ float g_h0[BATCH * 64];
__device__ float g_h1[BATCH * 512];
__device__ float g_h2[(size_t)BATCH * 1024];

// ---------------- helpers ----------------
__device__ __forceinline__ float warp_sum(float v) {
    #pragma unroll
    for (int s = 16; s > 0; s >>= 1) v += __shfl_xor_sync(0xFFFFFFFFu, v, s);
    return v;
}
__device__ __forceinline__ float sq8(float v) {   // sum v^2 over lanes differing in bits 2..4
    float t = v * v;
    t += __shfl_xor_sync(0xFFFFFFFFu, t, 4);
    t += __shfl_xor_sync(0xFFFFFFFFu, t, 8);
    t += __shfl_xor_sync(0xFFFFFFFFu, t, 16);
    return t;
}
__device__ __forceinline__ uint32_t smem_u32(const void* p) {
    return (uint32_t)__cvta_generic_to_shared(p);
}
__device__ __forceinline__ void ldsm_x4(uint32_t& r0, uint32_t& r1, uint32_t& r2, uint32_t& r3,
                                        uint32_t addr) {
    asm volatile("ldmatrix.sync.aligned.m8n8.x4.shared.b16 {%0,%1,%2,%3}, [%4];"
                 : "=r"(r0), "=r"(r1), "=r"(r2), "=r"(r3) : "r"(addr));
}
__device__ __forceinline__ void ldsm_x4_t(uint32_t& r0, uint32_t& r1, uint32_t& r2, uint32_t& r3,
                                          uint32_t addr) {
    asm volatile("ldmatrix.sync.aligned.m8n8.x4.trans.shared.b16 {%0,%1,%2,%3}, [%4];"
                 : "=r"(r0), "=r"(r1), "=r"(r2), "=r"(r3) : "r"(addr));
}
__device__ __forceinline__ void mma_bf16(float d[4], const uint32_t a[4],
                                         uint32_t b0, uint32_t b1) {
    asm volatile(
        "mma.sync.aligned.m16n8k16.row.col.f32.bf16.bf16.f32 "
        "{%0,%1,%2,%3}, {%4,%5,%6,%7}, {%8,%9}, {%0,%1,%2,%3};"
        : "+f"(d[0]), "+f"(d[1]), "+f"(d[2]), "+f"(d[3])
        : "r"(a[0]), "r"(a[1]), "r"(a[2]), "r"(a[3]), "r"(b0), "r"(b1));
}
__device__ __forceinline__ void cp_async16(uint32_t dst, const void* src) {
    asm volatile("cp.async.cg.shared.global [%0], [%1], 16;" :: "r"(dst), "l"(src) : "memory");
}

// ---------------- kernel: zero buffer ----------------
__global__ void zero_kernel(float* p, int n) {
    int i = blockIdx.x * blockDim.x + threadIdx.x;
    if (i < n) p[i] = 0.0f;
}

// ---------------- kernel: split prim weights into bf16 hi/lo [k][oc] ----------------
__global__ void wb_split_kernel(const float* __restrict__ pw) {
    int idx = blockIdx.x * blockDim.x + threadIdx.x;   // 147456
    if (idx >= 147456) return;
    int k = idx >> 6, oc = idx & 63;
    int j = k >> 8, ic = k & 255;
    float v = pw[oc * 2304 + ic * 9 + j];
    __nv_bfloat16 hi = __float2bfloat16(v);
    __nv_bfloat16 lo = __float2bfloat16(v - __bfloat162float(hi));
    g_wB_hi[idx] = hi;
    g_wB_lo[idx] = lo;
}

// ---------------- fused conv1 + tensor-core primary conv + squash ----------------
// one CTA per image, 512 threads (16 warps); warp = (mf = w&3) x (ng = w>>2)
__global__ void __launch_bounds__(512, 1) conv_tc_kernel(
    const float* __restrict__ data, const float* __restrict__ w1,
    const float* __restrict__ b1, const float* __restrict__ pb)
{
    extern __shared__ char smem[];
    __shared__ float s_img[64];
    __nv_bfloat16* xhi = (__nv_bfloat16*)(smem + XT_HI);
    __nv_bfloat16* xlo = (__nv_bfloat16*)(smem + XT_LO);

    int b = blockIdx.x;
    int tid = threadIdx.x;
    int w = tid >> 5, lane = tid & 31;
    uint32_t sm_base = smem_u32(smem);

    // ---- prefetch weight chunk 0 ----
    #pragma unroll
    for (int o = 0; o < 2; o++) {
        int idx = o * 512 + tid;
        int plane = idx >> 9, rem = idx & 511, r = rem >> 3, seg = rem & 7;
        const __nv_bfloat16* src = (plane ? g_wB_lo : g_wB_hi) + (size_t)r * 64 + seg * 8;
        uint32_t dst = sm_base + BBUF + plane * BPLANE + r * 144 + seg * 16;
        cp_async16(dst, src);
    }
    asm volatile("cp.async.commit_group;");

    // ---- zero the padded activation planes ----
    {
        uint4 z = make_uint4(0, 0, 0, 0);
        uint4* p = (uint4*)smem;
        for (int i = tid; i < (XT_LO * 2) / 16; i += 512) p[i] = z;
    }
    if (tid < 64) s_img[tid] = data[b * 64 + tid];
    __syncthreads();

    // ---- phase 1: conv1 (3x3, pad 1) + relu; 2 threads per ic, 4 rows each ----
    {
        int ic = tid & 255;
        int half = tid >> 8;
        float wr[9];
        #pragma unroll
        for (int k = 0; k < 9; k++) wr[k] = w1[ic * 9 + k];
        float bias = b1[ic];
        #pragma unroll
        for (int yy = 0; yy < 4; yy++) {
            int y = half * 4 + yy;
            #pragma unroll
            for (int x = 0; x < 8; x++) {
                float acc = bias;
                #pragma unroll
                for (int ky = 0; ky < 3; ky++) {
                    int iy = y + ky - 1;
                    if (iy < 0 || iy > 7) continue;
                    #pragma unroll
                    for (int kx = 0; kx < 3; kx++) {
                        int ix = x + kx - 1;
                        if (ix < 0 || ix > 7) continue;
                        acc += wr[ky * 3 + kx] * s_img[iy * 8 + ix];
                    }
                }
                acc = fmaxf(acc, 0.0f);
                __nv_bfloat16 hi = __float2bfloat16(acc);
                __nv_bfloat16 lo = __float2bfloat16(acc - __bfloat162float(hi));
                int p = (y + 1) * 16 + (x + 1);
                xhi[p * XROW + ic] = hi;
                xlo[p * XROW + ic] = lo;
            }
        }
    }
    // (first loop-iteration barrier publishes phase-1 writes)

    // ---- MMA mainloop: warp tile m16 x n16 ----
    int mf = w & 3, ng = w >> 2;
    int mloc = lane & 15, chalf = lane >> 4;
    int m = mf * 16 + mloc;
    int pbase = (m >> 3) * 16 + (m & 7);

    float d0[4] = {0.f, 0.f, 0.f, 0.f};
    float d1[4] = {0.f, 0.f, 0.f, 0.f};

    uint32_t xhi_u = sm_base + XT_HI;
    const int lo_delta = XT_LO - XT_HI;

    for (int cid = 0; cid < 36; cid++) {
        int buf = cid & 1;
        int js = cid >> 2, kc = cid & 3;
        int ky = js / 3, kx = js - ky * 3;

        asm volatile("cp.async.wait_group 0;");
        __syncthreads();   // chunk cid visible; all warps done with buf^1

        if (cid + 1 < 36) {   // prefetch next chunk into buf^1 (overlaps compute)
            int njs = (cid + 1) >> 2, nkc = (cid + 1) & 3;
            int krow0 = njs * 256 + nkc * 64;
            #pragma unroll
            for (int o = 0; o < 2; o++) {
                int idx = o * 512 + tid;
                int plane = idx >> 9, rem = idx & 511, r = rem >> 3, seg = rem & 7;
                const __nv_bfloat16* src =
                    (plane ? g_wB_lo : g_wB_hi) + (size_t)(krow0 + r) * 64 + seg * 8;
                uint32_t dst = sm_base + BBUF + (buf ^ 1) * BBUFSZ + plane * BPLANE
                               + r * 144 + seg * 16;
                cp_async16(dst, src);
            }
            asm volatile("cp.async.commit_group;");
        }

        uint32_t bbase = sm_base + BBUF + buf * BBUFSZ;
        int ashift = (pbase + ky * 16 + kx) * XROW;

        #pragma unroll
        for (int k16 = 0; k16 < 4; k16++) {
            int ic0 = kc * 64 + k16 * 16;
            uint32_t ah[4], al[4];
            uint32_t aaddr = xhi_u + (uint32_t)(ashift + ic0 + chalf * 8) * 2u;
            ldsm_x4(ah[0], ah[1], ah[2], ah[3], aaddr);
            ldsm_x4(al[0], al[1], al[2], al[3], aaddr + lo_delta);
            uint32_t bh[4], bl[4];
            uint32_t brow = bbase + (uint32_t)(k16 * 16 + mloc) * 144u;
            uint32_t baddr = brow + (uint32_t)(ng * 16 + chalf * 8) * 2u;
            ldsm_x4_t(bh[0], bh[1], bh[2], bh[3], baddr);
            ldsm_x4_t(bl[0], bl[1], bl[2], bl[3], baddr + BPLANE);
            // term-major: interleave the two accumulator chains
            mma_bf16(d0, ah, bh[0], bh[1]);
            mma_bf16(d1, ah, bh[2], bh[3]);
            mma_bf16(d0, ah, bl[0], bl[1]);
            mma_bf16(d1, ah, bl[2], bl[3]);
            mma_bf16(d0, al, bh[0], bh[1]);
            mma_bf16(d1, al, bh[2], bh[3]);
        }
    }

    // ---- epilogue: bias + squash + store u ----
    {
        int tig = lane & 3, gid = lane >> 2;   // x = gid, y = 2*mf (+1)
        float* dst = g_u + (size_t)b * RI;
        #pragma unroll
        for (int f = 0; f < 2; f++) {
            const float* d = f ? d1 : d0;
            int oc = ng * 16 + f * 8 + 2 * tig;
            float b0 = pb[oc], b1v = pb[oc + 1];
            float v00 = d[0] + b0, v01 = d[1] + b1v;
            float v10 = d[2] + b0, v11 = d[3] + b1v;
            float q00 = sq8(v00), q01 = sq8(v01), q10 = sq8(v10), q11 = sq8(v11);
            float s00 = q00 / ((1.0f + q00) * sqrtf(q00 + 1e-9f));
            float s01 = q01 / ((1.0f + q01) * sqrtf(q01 + 1e-9f));
            float s10 = q10 / ((1.0f + q10) * sqrtf(q10 + 1e-9f));
            float s11 = q11 / ((1.0f + q11) * sqrtf(q11 + 1e-9f));
            int y0 = 2 * mf;
            dst[(oc * 8 + y0) * 8 + gid]           = v00 * s00;
            dst[((oc + 1) * 8 + y0) * 8 + gid]     = v01 * s01;
            dst[(oc * 8 + y0 + 1) * 8 + gid]       = v10 * s10;
            dst[((oc + 1) * 8 + y0 + 1) * 8 + gid] = v11 * s11;
        }
    }
}

// ---------------- kernel: softmax of b over routes (axis 0) ----------------
__global__ void softmax_routes_kernel() {
    __shared__ float red[512];
    int t = threadIdx.x;
    for (int o = 0; o < 2; o++) {
        float val = g_bij[t * 2 + o];
        red[t] = val; __syncthreads();
        for (int s = 256; s > 0; s >>= 1) {
            if (t < s) red[t] = fmaxf(red[t], red[t + s]);
            __syncthreads();
        }
        float mx = red[0]; __syncthreads();
        float e = expf(val - mx);
        red[t] = e; __syncthreads();
        for (int s = 256; s > 0; s >>= 1) {
            if (t < s) red[t] += red[t + s];
            __syncthreads();
        }
        float sum = red[0]; __syncthreads();
        g_c[t * 2 + o] = e / sum;
    }
}

// ---------------- kernel: build WcT ----------------
__global__ void build_wct_kernel(const float* __restrict__ W) {
    int idx = blockIdx.x * blockDim.x + threadIdx.x;
    if (idx >= RI * OD) return;
    int od = idx & 63, ri = idx >> 6;
    int r = ri >> 3, i = ri & 7, o = od >> 5, dd = od & 31;
    g_WcT[idx] = g_c[r * 2 + o] * W[((r * 2 + o) * 32 + dd) * 8 + i];
}

// ---------------- GEMM: C = act(A*B + bias) ----------------
__global__ void __launch_bounds__(256) gemm_ab_kernel(
    const float* __restrict__ A, const float* __restrict__ B,
    const float* __restrict__ bias, float* __restrict__ C,
    int M, int N, int K, int act)
{
    __shared__ float As[16][68];
    __shared__ float Bs[16][64];
    int tid = threadIdx.x;
    int n0 = blockIdx.x * 64, m0 = blockIdx.y * 64;
    int tx = tid & 15, ty = tid >> 4;
    float acc[4][4] = {};

    for (int k0 = 0; k0 < K; k0 += 16) {
        #pragma unroll
        for (int l = 0; l < 4; l++) {
            int lin = tid + l * 256;
            int kk = lin & 15, mm = lin >> 4;
            As[kk][mm] = A[(size_t)(m0 + mm) * K + k0 + kk];
            int nn = lin & 63, kb = lin >> 6;
            Bs[kb][nn] = B[(size_t)(k0 + kb) * N + n0 + nn];
        }
        __syncthreads();
        #pragma unroll
        for (int kk = 0; kk < 16; kk++) {
            float4 a = *(const float4*)&As[kk][ty * 4];
            float4 bv = *(const float4*)&Bs[kk][tx * 4];
            float av[4] = {a.x, a.y, a.z, a.w};
            float bb[4] = {bv.x, bv.y, bv.z, bv.w};
            #pragma unroll
            for (int i = 0; i < 4; i++)
                #pragma unroll
                for (int j = 0; j < 4; j++) acc[i][j] += av[i] * bb[j];
        }
        __syncthreads();
    }
    #pragma unroll
    for (int i = 0; i < 4; i++) {
        int mm = m0 + ty * 4 + i;
        #pragma unroll
        for (int j = 0; j < 4; j++) {
            int nn = n0 + tx * 4 + j;
            float v = acc[i][j] + (bias ? bias[nn] : 0.0f);
            if (act == 1) v = fmaxf(v, 0.0f);
            else if (act == 2) v = 1.0f / (1.0f + expf(-v));
            C[(size_t)mm * N + nn] = v;
        }
    }
}

// ---------------- GEMM split-K (atomic): C += A*B ----------------
__global__ void __launch_bounds__(256) gemm_ab_splitk_kernel(
    const float* __restrict__ A, const float* __restrict__ B, float* __restrict__ C,
    int M, int N, int lda, int Kchunk)
{
    __shared__ float As[16][68];
    __shared__ float Bs[16][64];
    int tid = threadIdx.x;
    int n0 = blockIdx.x * 64, m0 = blockIdx.y * 64;
    int kbase = blockIdx.z * Kchunk;
    int tx = tid & 15, ty = tid >> 4;
    float acc[4][4] = {};

    for (int k0 = 0; k0 < Kchunk; k0 += 16) {
        #pragma unroll
        for (int l = 0; l < 4; l++) {
            int lin = tid + l * 256;
            int kk = lin & 15, mm = lin >> 4;
            As[kk][mm] = A[(size_t)(m0 + mm) * lda + kbase + k0 + kk];
            int nn = lin & 63, kb = lin >> 6;
            Bs[kb][nn] = B[(size_t)(kbase + k0 + kb) * N + n0 + nn];
        }
        __syncthreads();
        #pragma unroll
        for (int kk = 0; kk < 16; kk++) {
            float4 a = *(const float4*)&As[kk][ty * 4];
            float4 bv = *(const float4*)&Bs[kk][tx * 4];
            float av[4] = {a.x, a.y, a.z, a.w};
            float bb[4] = {bv.x, bv.y, bv.z, bv.w};
            #pragma unroll
            for (int i = 0; i < 4; i++)
                #pragma unroll
                for (int j = 0; j < 4; j++) acc[i][j] += av[i] * bb[j];
        }
        __syncthreads();
    }
    #pragma unroll
    for (int i = 0; i < 4; i++) {
        int mm = m0 + ty * 4 + i;
        #pragma unroll
        for (int j = 0; j < 4; j++) {
            int nn = n0 + tx * 4 + j;
            atomicAdd(&C[(size_t)mm * N + nn], acc[i][j]);
        }
    }
}

// ---------------- GEMM split-K (atomic): C += alpha * A^T * B ----------------
__global__ void __launch_bounds__(256) gemm_atb_splitk_kernel(
    const float* __restrict__ A, const float* __restrict__ B, float* __restrict__ C,
    int M, int N, int Kchunk, float alpha)
{
    __shared__ float As[16][68];
    __shared__ float Bs[16][64];
    int tid = threadIdx.x;
    int n0 = blockIdx.x * 64, m0 = blockIdx.y * 64;
    int kbase = blockIdx.z * Kchunk;
    int tx = tid & 15, ty = tid >> 4;
    float acc[4][4] = {};

    for (int k0 = 0; k0 < Kchunk; k0 += 16) {
        #pragma unroll
        for (int l = 0; l < 4; l++) {
            int lin = tid + l * 256;
            int mm = lin & 63, kk = lin >> 6;
            As[kk][mm] = A[(size_t)(kbase + k0 + kk) * M + m0 + mm];
            Bs[kk][mm] = B[(size_t)(kbase + k0 + kk) * N + n0 + mm];
        }
        __syncthreads();
        #pragma unroll
        for (int kk = 0; kk < 16; kk++) {
            float4 a = *(const float4*)&As[kk][ty * 4];
            float4 bv = *(const float4*)&Bs[kk][tx * 4];
            float av[4] = {a.x, a.y, a.z, a.w};
            float bb[4] = {bv.x, bv.y, bv.z, bv.w};
            #pragma unroll
            for (int i = 0; i < 4; i++)
                #pragma unroll
                for (int j = 0; j < 4; j++) acc[i][j] += av[i] * bb[j];
        }
        __syncthreads();
    }
    #pragma unroll
    for (int i = 0; i < 4; i++) {
        int mm = m0 + ty * 4 + i;
        #pragma unroll
        for (int j = 0; j < 4; j++) {
            int nn = n0 + tx * 4 + j;
            atomicAdd(&C[(size_t)mm * N + nn], alpha * acc[i][j]);
        }
    }
}

// ---------------- kernel: squash 32-vectors of s -> v ----------------
__global__ void squash_v_kernel() {
    int gid = blockIdx.x * blockDim.x + threadIdx.x;
    int warp = gid >> 5;
    int lane = gid & 31;
    if (warp >= BATCH * 2) return;
    int b = warp >> 1, o = warp & 1;
    float x = g_s[b * 64 + o * 32 + lane];
    float sq = warp_sum(x * x);
    float sc = sq / ((1.0f + sq) * sqrtf(sq + 1e-9f));
    g_v[b * 64 + o * 32 + lane] = x * sc;
}

// ---------------- kernel: b_ij update ----------------
__global__ void b_update_kernel(const float* __restrict__ W) {
    int gid = blockIdx.x * blockDim.x + threadIdx.x;
    int warp = gid >> 5;
    int lane = gid & 31;
    if (warp >= NR * 2) return;
    int r = warp >> 1, o = warp & 1;
    float sum = 0.0f;
    for (int t = lane; t < 256; t += 32) {
        int dd = t >> 3, i = t & 7;
        sum += W[(r * 2 + o) * 256 + t] * g_G[(r * 8 + i) * 64 + o * 32 + dd];
    }
    sum = warp_sum(sum);
    if (lane == 0) g_bij[r * 2 + o] += sum;
}

// ---------------- kernel: mask / argmax / output write ----------------
__global__ void mask_kernel(float* __restrict__ out) {
    int gid = blockIdx.x * blockDim.x + threadIdx.x;
    int b = gid >> 5;
    int lane = gid & 31;
    if (b >= BATCH) return;
    float v0 = g_v[b * 64 + lane];
    float v1 = g_v[b * 64 + 32 + lane];
    float n0 = warp_sum(v0 * v0);
    float n1 = warp_sum(v1 * v1);
    int idx = (n1 > n0) ? 1 : 0;
    float m0 = (idx == 0) ? 1.0f : 0.0f;
    float m1 = 1.0f - m0;
    out[OUT_V_OFF + b * 64 + lane]       = v0;
    out[OUT_V_OFF + b * 64 + 32 + lane]  = v1;
    if (lane == 0) {
        out[OUT_MASK_OFF + b * 2 + 0] = m0;
        out[OUT_MASK_OFF + b * 2 + 1] = m1;
    }
    g_h0[b * 64 + lane]      = v0 * m0;
    g_h0[b * 64 + 32 + lane] = v1 * m1;
}

// ---------------- kernel: dec3 epilogue: out = sigmoid(acc + bias) ----------------
__global__ void sigmoid_bias_kernel(const float* __restrict__ bias, float* __restrict__ out) {
    int i = blockIdx.x * blockDim.x + threadIdx.x;
    if (i >= BATCH * 64) return;
    float v = g_r[i] + bias[i & 63];
    out[OUT_REC_OFF + i] = 1.0f / (1.0f + expf(-v));
}

// ---------------- launch ----------------
extern "C" void kernel_launch(void* const* d_in, const int* in_sizes, int n_in,
                              void* d_out, int out_size)
{
    const float* data    = (const float*)d_in[0];
    const float* conv1_w = (const float*)d_in[1];
    const float* conv1_b = (const float*)d_in[2];
    const float* prim_w  = (const float*)d_in[3];
    const float* prim_b  = (const float*)d_in[4];
    const float* W_digit = (const float*)d_in[5];
    const float* dec1_w  = (const float*)d_in[6];
    const float* dec1_b  = (const float*)d_in[7];
    const float* dec2_w  = (const float*)d_in[8];
    const float* dec2_b  = (const float*)d_in[9];
    const float* dec3_w  = (const float*)d_in[10];
    const float* dec3_b  = (const float*)d_in[11];
    float* out = (float*)d_out;

    float *p_bij, *p_s, *p_G, *p_u, *p_WcT, *p_v, *p_r, *p_h0, *p_h1, *p_h2;
    cudaGetSymbolAddress((void**)&p_bij, g_bij);
    cudaGetSymbolAddress((void**)&p_s,   g_s);
    cudaGetSymbolAddress((void**)&p_G,   g_G);
    cudaGetSymbolAddress((void**)&p_u,   g_u);
    cudaGetSymbolAddress((void**)&p_WcT, g_WcT);
    cudaGetSymbolAddress((void**)&p_v,   g_v);
    cudaGetSymbolAddress((void**)&p_r,   g_r);
    cudaGetSymbolAddress((void**)&p_h0,  g_h0);
    cudaGetSymbolAddress((void**)&p_h1,  g_h1);
    cudaGetSymbolAddress((void**)&p_h2,  g_h2);

    static int smem_set = 0;
    if (!smem_set) {
        cudaFuncSetAttribute(conv_tc_kernel,
                             cudaFuncAttributeMaxDynamicSharedMemorySize, CONV_SMEM);
        smem_set = 1;
    }

    // prep (launch indices 0..4; conv_tc lands at index 5 for ncu -s 5 -c 1)
    wb_split_kernel<<<576, 256>>>(prim_w);                           // 0
    zero_kernel<<<4, 256>>>(p_bij, NR * 2);                          // 1
    zero_kernel<<<512, 256>>>(p_s, BATCH * 32);                      // 2
    zero_kernel<<<512, 256>>>(p_s + BATCH * 32, BATCH * 32);         // 3
    zero_kernel<<<1024, 256>>>(p_G, RI * 64);                        // 4

    // fused conv1 + tensor-core primary caps + squash -> g_u
    conv_tc_kernel<<<BATCH, 512, CONV_SMEM>>>(data, conv1_w, conv1_b, prim_b);  // 5

    // dynamic routing, 3 iterations
    for (int it = 0; it < 3; it++) {
        softmax_routes_kernel<<<1, 512>>>();
        build_wct_kernel<<<1024, 256>>>(W_digit);
        if (it > 0) zero_kernel<<<1024, 256>>>(p_s, BATCH * 64);
        gemm_ab_splitk_kernel<<<dim3(1, 64, 8), 256>>>(p_u, p_WcT, p_s,
                                                       BATCH, 64, RI, 512);
        squash_v_kernel<<<1024, 256>>>();
        if (it < 2) {
            if (it > 0) zero_kernel<<<1024, 256>>>(p_G, RI * 64);
            gemm_atb_splitk_kernel<<<dim3(1, 64, 8), 256>>>(p_u, p_v, p_G,
                                                            RI, 64, 512,
                                                            1.0f / (float)BATCH);
            b_update_kernel<<<128, 256>>>(W_digit);
        }
    }

    mask_kernel<<<512, 256>>>(out);
    zero_kernel<<<1024, 256>>>(p_r, BATCH * 64);

    // decoder
    gemm_ab_kernel<<<dim3(8, 64), 256>>>(p_h0, dec1_w, dec1_b, p_h1,
                                         BATCH, 512, 64, 1);
    gemm_ab_kernel<<<dim3(16, 64), 256>>>(p_h1, dec2_w, dec2_b, p_h2,
                                          BATCH, 1024, 512, 1);
    gemm_ab_splitk_kernel<<<dim3(1, 64, 4), 256>>>(p_h2, dec3_w, p_r,
                                                   BATCH, 64, 1024, 256);
    sigmoid_bias_kernel<<<1024, 256>>>(dec3_b, out);
}

// round 9
// speedup vs baseline: 1.2087x; 1.2087x over previous
#include <cuda_runtime.h>
#include <cuda_bf16.h>
#include <math.h>
#include <stdint.h>

#define BATCH 4096
#define NR 512
#define RI 4096
#define OD 64
#define OUT_REC_OFF 262144
#define OUT_MASK_OFF 524288

// conv-kernel SMEM layout (bytes)
#define XROW 264
#define XT_HI 0
#define XT_LO 84480
#define BBUF  168960
#define BPLANE 9216
#define BBUFSZ 18432
#define CONV_SMEM 205824

// mma-GEMM smem layout (bytes): A 64x32 bf16 pitch 80, B 32x64 bf16 pitch 144
#define GAH 0
#define GAL 5120
#define GBH 10240
#define GBL 14848
#define GSMB 19456

__device__ __nv_bfloat16 g_wB_hi[2304 * 64];
__device__ __nv_bfloat16 g_wB_lo[2304 * 64];
__device__ float g_u[(size_t)BATCH * RI];
__device__ float g_WcT[RI * OD];
__device__ float g_bij[NR * 2];
__device__ float g_c[NR * 2];
__device__ float g_s[BATCH * OD];
__device__ float g_v[BATCH * OD];
__device__ float g_G[RI * OD];
__device__ float g_r[BATCH * 64];
__device__ float g_h0[BATCH * 64];
__device__ float g_h1[BATCH * 512];
__device__ float g_h2[(size_t)BATCH * 1024];

// ---------------- helpers ----------------
__device__ __forceinline__ float warp_sum(float v) {
    #pragma unroll
    for (int s = 16; s > 0; s >>= 1) v += __shfl_xor_sync(0xFFFFFFFFu, v, s);
    return v;
}
__device__ __forceinline__ float sq8(float v) {
    float t = v * v;
    t += __shfl_xor_sync(0xFFFFFFFFu, t, 4);
    t += __shfl_xor_sync(0xFFFFFFFFu, t, 8);
    t += __shfl_xor_sync(0xFFFFFFFFu, t, 16);
    return t;
}
__device__ __forceinline__ uint32_t smem_u32(const void* p) {
    return (uint32_t)__cvta_generic_to_shared(p);
}
__device__ __forceinline__ void ldsm_x4(uint32_t& r0, uint32_t& r1, uint32_t& r2, uint32_t& r3,
                                        uint32_t addr) {
    asm volatile("ldmatrix.sync.aligned.m8n8.x4.shared.b16 {%0,%1,%2,%3}, [%4];"
                 : "=r"(r0), "=r"(r1), "=r"(r2), "=r"(r3) : "r"(addr));
}
__device__ __forceinline__ void ldsm_x4_t(uint32_t& r0, uint32_t& r1, uint32_t& r2, uint32_t& r3,
                                          uint32_t addr) {
    asm volatile("ldmatrix.sync.aligned.m8n8.x4.trans.shared.b16 {%0,%1,%2,%3}, [%4];"
                 : "=r"(r0), "=r"(r1), "=r"(r2), "=r"(r3) : "r"(addr));
}
__device__ __forceinline__ void mma_bf16(float d[4], const uint32_t a[4],
                                         uint32_t b0, uint32_t b1) {
    asm volatile(
        "mma.sync.aligned.m16n8k16.row.col.f32.bf16.bf16.f32 "
        "{%0,%1,%2,%3}, {%4,%5,%6,%7}, {%8,%9}, {%0,%1,%2,%3};"
        : "+f"(d[0]), "+f"(d[1]), "+f"(d[2]), "+f"(d[3])
        : "r"(a[0]), "r"(a[1]), "r"(a[2]), "r"(a[3]), "r"(b0), "r"(b1));
}
__device__ __forceinline__ void cp_async16(uint32_t dst, const void* src) {
    asm volatile("cp.async.cg.shared.global [%0], [%1], 16;" :: "r"(dst), "l"(src) : "memory");
}
__device__ __forceinline__ void pack8(const float* fa, uint4& h, uint4& l) {
    uint32_t hp[4], lp[4];
    #pragma unroll
    for (int q = 0; q < 4; q++) {
        float a0 = fa[2 * q], a1 = fa[2 * q + 1];
        __nv_bfloat16 h0 = __float2bfloat16(a0), h1 = __float2bfloat16(a1);
        __nv_bfloat16 l0 = __float2bfloat16(a0 - __bfloat162float(h0));
        __nv_bfloat16 l1 = __float2bfloat16(a1 - __bfloat162float(h1));
        hp[q] = (uint32_t)__bfloat16_as_ushort(h0) | ((uint32_t)__bfloat16_as_ushort(h1) << 16);
        lp[q] = (uint32_t)__bfloat16_as_ushort(l0) | ((uint32_t)__bfloat16_as_ushort(l1) << 16);
    }
    h = make_uint4(hp[0], hp[1], hp[2], hp[3]);
    l = make_uint4(lp[0], lp[1], lp[2], lp[3]);
}

// ---------------- basic kernels ----------------
__global__ void zero_kernel(float* p, int n) {
    int i = blockIdx.x * blockDim.x + threadIdx.x;
    if (i < n) p[i] = 0.0f;
}

__global__ void wb_split_kernel(const float* __restrict__ pw) {
    int idx = blockIdx.x * blockDim.x + threadIdx.x;
    if (idx >= 147456) return;
    int k = idx >> 6, oc = idx & 63;
    int j = k >> 8, ic = k & 255;
    float v = pw[oc * 2304 + ic * 9 + j];
    __nv_bfloat16 hi = __float2bfloat16(v);
    __nv_bfloat16 lo = __float2bfloat16(v - __bfloat162float(hi));
    g_wB_hi[idx] = hi;
    g_wB_lo[idx] = lo;
}

// ---------------- fused conv1 + mma.sync primary conv + squash (R6, proven) ----
__global__ void __launch_bounds__(512, 1) conv_tc_kernel(
    const float* __restrict__ data, const float* __restrict__ w1,
    const float* __restrict__ b1, const float* __restrict__ pb)
{
    extern __shared__ char smem[];
    __shared__ float s_img[64];
    __nv_bfloat16* xhi = (__nv_bfloat16*)(smem + XT_HI);
    __nv_bfloat16* xlo = (__nv_bfloat16*)(smem + XT_LO);

    int b = blockIdx.x;
    int tid = threadIdx.x;
    int w = tid >> 5, lane = tid & 31;
    uint32_t sm_base = smem_u32(smem);

    #pragma unroll
    for (int o = 0; o < 2; o++) {
        int idx = o * 512 + tid;
        int plane = idx >> 9, rem = idx & 511, r = rem >> 3, seg = rem & 7;
        const __nv_bfloat16* src = (plane ? g_wB_lo : g_wB_hi) + (size_t)r * 64 + seg * 8;
        cp_async16(sm_base + BBUF + plane * BPLANE + r * 144 + seg * 16, src);
    }
    asm volatile("cp.async.commit_group;");

    {
        uint4 z = make_uint4(0, 0, 0, 0);
        uint4* p = (uint4*)smem;
        for (int i = tid; i < (XT_LO * 2) / 16; i += 512) p[i] = z;
    }
    if (tid < 64) s_img[tid] = data[b * 64 + tid];
    __syncthreads();

    {
        int ic = tid & 255, half = tid >> 8;
        float wr[9];
        #pragma unroll
        for (int k = 0; k < 9; k++) wr[k] = w1[ic * 9 + k];
        float bias = b1[ic];
        #pragma unroll
        for (int yy = 0; yy < 4; yy++) {
            int y = half * 4 + yy;
            #pragma unroll
            for (int x = 0; x < 8; x++) {
                float acc = bias;
                #pragma unroll
                for (int ky = 0; ky < 3; ky++) {
                    int iy = y + ky - 1;
                    if (iy < 0 || iy > 7) continue;
                    #pragma unroll
                    for (int kx = 0; kx < 3; kx++) {
                        int ix = x + kx - 1;
                        if (ix < 0 || ix > 7) continue;
                        acc += wr[ky * 3 + kx] * s_img[iy * 8 + ix];
                    }
                }
                acc = fmaxf(acc, 0.0f);
                __nv_bfloat16 hi = __float2bfloat16(acc);
                __nv_bfloat16 lo = __float2bfloat16(acc - __bfloat162float(hi));
                int p = (y + 1) * 16 + (x + 1);
                xhi[p * XROW + ic] = hi;
                xlo[p * XROW + ic] = lo;
            }
        }
    }

    int mf = w & 3, ng = w >> 2;
    int mloc = lane & 15, chalf = lane >> 4;
    int m = mf * 16 + mloc;
    int pbase = (m >> 3) * 16 + (m & 7);

    float d0[4] = {0.f, 0.f, 0.f, 0.f};
    float d1[4] = {0.f, 0.f, 0.f, 0.f};
    uint32_t xhi_u = sm_base + XT_HI;
    const int lo_delta = XT_LO - XT_HI;

    for (int cid = 0; cid < 36; cid++) {
        int buf = cid & 1;
        int js = cid >> 2, kc = cid & 3;
        int ky = js / 3, kx = js - ky * 3;

        asm volatile("cp.async.wait_group 0;");
        __syncthreads();

        if (cid + 1 < 36) {
            int njs = (cid + 1) >> 2, nkc = (cid + 1) & 3;
            int krow0 = njs * 256 + nkc * 64;
            #pragma unroll
            for (int o = 0; o < 2; o++) {
                int idx = o * 512 + tid;
                int plane = idx >> 9, rem = idx & 511, r = rem >> 3, seg = rem & 7;
                const __nv_bfloat16* src =
                    (plane ? g_wB_lo : g_wB_hi) + (size_t)(krow0 + r) * 64 + seg * 8;
                cp_async16(sm_base + BBUF + (buf ^ 1) * BBUFSZ + plane * BPLANE
                           + r * 144 + seg * 16, src);
            }
            asm volatile("cp.async.commit_group;");
        }

        uint32_t bbase = sm_base + BBUF + buf * BBUFSZ;
        int ashift = (pbase + ky * 16 + kx) * XROW;

        #pragma unroll
        for (int k16 = 0; k16 < 4; k16++) {
            int ic0 = kc * 64 + k16 * 16;
            uint32_t ah[4], al[4];
            uint32_t aaddr = xhi_u + (uint32_t)(ashift + ic0 + chalf * 8) * 2u;
            ldsm_x4(ah[0], ah[1], ah[2], ah[3], aaddr);
            ldsm_x4(al[0], al[1], al[2], al[3], aaddr + lo_delta);
            uint32_t bh[4], bl[4];
            uint32_t baddr = bbase + (uint32_t)(k16 * 16 + mloc) * 144u
                           + (uint32_t)(ng * 16 + chalf * 8) * 2u;
            ldsm_x4_t(bh[0], bh[1], bh[2], bh[3], baddr);
            ldsm_x4_t(bl[0], bl[1], bl[2], bl[3], baddr + BPLANE);
            mma_bf16(d0, ah, bh[0], bh[1]);
            mma_bf16(d1, ah, bh[2], bh[3]);
            mma_bf16(d0, ah, bl[0], bl[1]);
            mma_bf16(d1, ah, bl[2], bl[3]);
            mma_bf16(d0, al, bh[0], bh[1]);
            mma_bf16(d1, al, bh[2], bh[3]);
        }
    }

    {
        int tig = lane & 3, gid = lane >> 2;
        float* dst = g_u + (size_t)b * RI;
        #pragma unroll
        for (int f = 0; f < 2; f++) {
            const float* d = f ? d1 : d0;
            int oc = ng * 16 + f * 8 + 2 * tig;
            float b0 = pb[oc], b1v = pb[oc + 1];
            float v00 = d[0] + b0, v01 = d[1] + b1v;
            float v10 = d[2] + b0, v11 = d[3] + b1v;
            float q00 = sq8(v00), q01 = sq8(v01), q10 = sq8(v10), q11 = sq8(v11);
            float s00 = q00 / ((1.0f + q00) * sqrtf(q00 + 1e-9f));
            float s01 = q01 / ((1.0f + q01) * sqrtf(q01 + 1e-9f));
            float s10 = q10 / ((1.0f + q10) * sqrtf(q10 + 1e-9f));
            float s11 = q11 / ((1.0f + q11) * sqrtf(q11 + 1e-9f));
            int y0 = 2 * mf;
            dst[(oc * 8 + y0) * 8 + gid]           = v00 * s00;
            dst[((oc + 1) * 8 + y0) * 8 + gid]     = v01 * s01;
            dst[(oc * 8 + y0 + 1) * 8 + gid]       = v10 * s10;
            dst[((oc + 1) * 8 + y0 + 1) * 8 + gid] = v11 * s11;
        }
    }
}

// ---------------- split-bf16 mma GEMM: staging + tile ----------------
__device__ __forceinline__ void stage_A_rm(const float* A, size_t lda, int m0, int k0,
                                           char* sm, int tid) {
    int m = tid >> 2, kq = (tid & 3) * 8;
    const float* p = A + (size_t)(m0 + m) * lda + k0 + kq;
    float4 f0 = *(const float4*)p, f1 = *(const float4*)(p + 4);
    float fa[8] = {f0.x, f0.y, f0.z, f0.w, f1.x, f1.y, f1.z, f1.w};
    uint4 h, l; pack8(fa, h, l);
    *(uint4*)(sm + GAH + m * 80 + kq * 2) = h;
    *(uint4*)(sm + GAL + m * 80 + kq * 2) = l;
}
__device__ __forceinline__ void stage_A_tr(const float* AT, size_t ldm, int m0, int k0,
                                           char* sm, int tid) {
    int k = tid >> 3, mq = (tid & 7) * 8;
    const float* p = AT + (size_t)(k0 + k) * ldm + m0 + mq;
    float4 f0 = *(const float4*)p, f1 = *(const float4*)(p + 4);
    float fa[8] = {f0.x, f0.y, f0.z, f0.w, f1.x, f1.y, f1.z, f1.w};
    #pragma unroll
    for (int i = 0; i < 8; i++) {
        __nv_bfloat16 h = __float2bfloat16(fa[i]);
        __nv_bfloat16 l = __float2bfloat16(fa[i] - __bfloat162float(h));
        *(__nv_bfloat16*)(sm + GAH + (mq + i) * 80 + k * 2) = h;
        *(__nv_bfloat16*)(sm + GAL + (mq + i) * 80 + k * 2) = l;
    }
}
__device__ __forceinline__ void stage_B(const float* B, size_t ldb, int k0, int n0,
                                        char* sm, int tid) {
    int k = tid >> 3, nq = (tid & 7) * 8;
    const float* p = B + (size_t)(k0 + k) * ldb + n0 + nq;
    float4 f0 = *(const float4*)p, f1 = *(const float4*)(p + 4);
    float fa[8] = {f0.x, f0.y, f0.z, f0.w, f1.x, f1.y, f1.z, f1.w};
    uint4 h, l; pack8(fa, h, l);
    *(uint4*)(sm + GBH + k * 144 + nq * 2) = h;
    *(uint4*)(sm + GBL + k * 144 + nq * 2) = l;
}
__device__ __forceinline__ void mma_tile(char* sm, int w, int lane, float (&d)[2][2][4]) {
    int mf = w & 3, ng = w >> 2;
    int mloc = lane & 15, chalf = lane >> 4;
    uint32_t smb = smem_u32(sm);
    #pragma unroll
    for (int ks = 0; ks < 2; ks++) {
        uint32_t ah[4], al[4];
        uint32_t aaddr = smb + GAH + (uint32_t)((mf * 16 + mloc) * 80 + (ks * 16 + chalf * 8) * 2);
        ldsm_x4(ah[0], ah[1], ah[2], ah[3], aaddr);
        ldsm_x4(al[0], al[1], al[2], al[3], aaddr + (GAL - GAH));
        #pragma unroll
        for (int h = 0; h < 2; h++) {
            uint32_t bh[4], bl[4];
            uint32_t baddr = smb + GBH
                + (uint32_t)((ks * 16 + mloc) * 144 + (ng * 32 + h * 16 + chalf * 8) * 2);
            ldsm_x4_t(bh[0], bh[1], bh[2], bh[3], baddr);
            ldsm_x4_t(bl[0], bl[1], bl[2], bl[3], baddr + (GBL - GBH));
            mma_bf16(d[h][0], ah, bh[0], bh[1]);
            mma_bf16(d[h][1], ah, bh[2], bh[3]);
            mma_bf16(d[h][0], ah, bl[0], bl[1]);
            mma_bf16(d[h][1], ah, bl[2], bl[3]);
            mma_bf16(d[h][0], al, bh[0], bh[1]);
            mma_bf16(d[h][1], al, bh[2], bh[3]);
        }
    }
}

// C += A@B, split-K atomic. grid (N/64, M/64, splits)
__global__ void __launch_bounds__(256) tgemm_rm_splitk(
    const float* __restrict__ A, const float* __restrict__ B, float* __restrict__ C,
    int lda, int N, int Kchunk)
{
    __shared__ char sm[GSMB];
    int tid = threadIdx.x, w = tid >> 5, lane = tid & 31;
    int n0 = blockIdx.x * 64, m0 = blockIdx.y * 64, kbase = blockIdx.z * Kchunk;
    float d[2][2][4] = {};
    for (int k0 = 0; k0 < Kchunk; k0 += 32) {
        __syncthreads();
        stage_A_rm(A, lda, m0, kbase + k0, sm, tid);
        stage_B(B, N, kbase + k0, n0, sm, tid);
        __syncthreads();
        mma_tile(sm, w, lane, d);
    }
    int mf = w & 3, ng = w >> 2;
    int tig = lane & 3, gid = lane >> 2;
    #pragma unroll
    for (int h = 0; h < 2; h++)
        #pragma unroll
        for (int f = 0; f < 2; f++) {
            int col = n0 + ng * 32 + h * 16 + f * 8 + 2 * tig;
            int row = m0 + mf * 16 + gid;
            atomicAdd(&C[(size_t)row * N + col],           d[h][f][0]);
            atomicAdd(&C[(size_t)row * N + col + 1],       d[h][f][1]);
            atomicAdd(&C[(size_t)(row + 8) * N + col],     d[h][f][2]);
            atomicAdd(&C[(size_t)(row + 8) * N + col + 1], d[h][f][3]);
        }
}

// C += alpha * A^T@B, A stored [K][Mtot], split-K atomic
__global__ void __launch_bounds__(256) tgemm_tr_splitk(
    const float* __restrict__ AT, const float* __restrict__ B, float* __restrict__ C,
    int ldm, int N, int Kchunk, float alpha)
{
    __shared__ char sm[GSMB];
    int tid = threadIdx.x, w = tid >> 5, lane = tid & 31;
    int n0 = blockIdx.x * 64, m0 = blockIdx.y * 64, kbase = blockIdx.z * Kchunk;
    float d[2][2][4] = {};
    for (int k0 = 0; k0 < Kchunk; k0 += 32) {
        __syncthreads();
        stage_A_tr(AT, ldm, m0, kbase + k0, sm, tid);
        stage_B(B, N, kbase + k0, n0, sm, tid);
        __syncthreads();
        mma_tile(sm, w, lane, d);
    }
    int mf = w & 3, ng = w >> 2;
    int tig = lane & 3, gid = lane >> 2;
    #pragma unroll
    for (int h = 0; h < 2; h++)
        #pragma unroll
        for (int f = 0; f < 2; f++) {
            int col = n0 + ng * 32 + h * 16 + f * 8 + 2 * tig;
            int row = m0 + mf * 16 + gid;
            atomicAdd(&C[(size_t)row * N + col],           alpha * d[h][f][0]);
            atomicAdd(&C[(size_t)row * N + col + 1],       alpha * d[h][f][1]);
            atomicAdd(&C[(size_t)(row + 8) * N + col],     alpha * d[h][f][2]);
            atomicAdd(&C[(size_t)(row + 8) * N + col + 1], alpha * d[h][f][3]);
        }
}

// C = act(A@B + bias), full K. act: 1=relu
__global__ void __launch_bounds__(256) tgemm_rm_bias(
    const float* __restrict__ A, const float* __restrict__ B,
    const float* __restrict__ bias, float* __restrict__ C, int K, int N, int act)
{
    __shared__ char sm[GSMB];
    int tid = threadIdx.x, w = tid >> 5, lane = tid & 31;
    int n0 = blockIdx.x * 64, m0 = blockIdx.y * 64;
    float d[2][2][4] = {};
    for (int k0 = 0; k0 < K; k0 += 32) {
        __syncthreads();
        stage_A_rm(A, K, m0, k0, sm, tid);
        stage_B(B, N, k0, n0, sm, tid);
        __syncthreads();
        mma_tile(sm, w, lane, d);
    }
    int mf = w & 3, ng = w >> 2;
    int tig = lane & 3, gid = lane >> 2;
    #pragma unroll
    for (int h = 0; h < 2; h++)
        #pragma unroll
        for (int f = 0; f < 2; f++) {
            int col = n0 + ng * 32 + h * 16 + f * 8 + 2 * tig;
            int row = m0 + mf * 16 + gid;
            #pragma unroll
            for (int e = 0; e < 4; e++) {
                int rr = row + (e >> 1) * 8;
                int cc = col + (e & 1);
                float v = d[h][f][e] + bias[cc];
                if (act == 1) v = fmaxf(v, 0.0f);
                C[(size_t)rr * N + cc] = v;
            }
        }
}

// ---------------- routing small kernels ----------------
__global__ void softmax_routes_kernel() {
    __shared__ float red[512];
    int t = threadIdx.x;
    for (int o = 0; o < 2; o++) {
        float val = g_bij[t * 2 + o];
        red[t] = val; __syncthreads();
        for (int s = 256; s > 0; s >>= 1) {
            if (t < s) red[t] = fmaxf(red[t], red[t + s]);
            __syncthreads();
        }
        float mx = red[0]; __syncthreads();
        float e = expf(val - mx);
        red[t] = e; __syncthreads();
        for (int s = 256; s > 0; s >>= 1) {
            if (t < s) red[t] += red[t + s];
            __syncthreads();
        }
        float sum = red[0]; __syncthreads();
        g_c[t * 2 + o] = e / sum;
    }
}

__global__ void build_wct_kernel(const float* __restrict__ W) {
    int idx = blockIdx.x * blockDim.x + threadIdx.x;
    if (idx >= RI * OD) return;
    int od = idx & 63, ri = idx >> 6;
    int r = ri >> 3, i = ri & 7, o = od >> 5, dd = od & 31;
    g_WcT[idx] = g_c[r * 2 + o] * W[((r * 2 + o) * 32 + dd) * 8 + i];
}

__global__ void squash_v_kernel() {
    int gid = blockIdx.x * blockDim.x + threadIdx.x;
    int warp = gid >> 5, lane = gid & 31;
    if (warp >= BATCH * 2) return;
    int b = warp >> 1, o = warp & 1;
    float x = g_s[b * 64 + o * 32 + lane];
    float sq = warp_sum(x * x);
    float sc = sq / ((1.0f + sq) * sqrtf(sq + 1e-9f));
    g_v[b * 64 + o * 32 + lane] = x * sc;
}

__global__ void b_update_kernel(const float* __restrict__ W) {
    int gid = blockIdx.x * blockDim.x + threadIdx.x;
    int warp = gid >> 5, lane = gid & 31;
    if (warp >= NR * 2) return;
    int r = warp >> 1, o = warp & 1;
    float sum = 0.0f;
    for (int t = lane; t < 256; t += 32) {
        int dd = t >> 3, i = t & 7;
        sum += W[(r * 2 + o) * 256 + t] * g_G[(r * 8 + i) * 64 + o * 32 + dd];
    }
    sum = warp_sum(sum);
    if (lane == 0) g_bij[r * 2 + o] += sum;
}

__global__ void mask_kernel(float* __restrict__ out) {
    int gid = blockIdx.x * blockDim.x + threadIdx.x;
    int b = gid >> 5, lane = gid & 31;
    if (b >= BATCH) return;
    float v0 = g_v[b * 64 + lane];
    float v1 = g_v[b * 64 + 32 + lane];
    float n0 = warp_sum(v0 * v0);
    float n1 = warp_sum(v1 * v1);
    float m0 = (n1 > n0) ? 0.0f : 1.0f;
    float m1 = 1.0f - m0;
    out[b * 64 + lane] = v0;
    out[b * 64 + 32 + lane] = v1;
    if (lane == 0) {
        out[OUT_MASK_OFF + b * 2 + 0] = m0;
        out[OUT_MASK_OFF + b * 2 + 1] = m1;
    }
    g_h0[b * 64 + lane] = v0 * m0;
    g_h0[b * 64 + 32 + lane] = v1 * m1;
}

__global__ void sigmoid_bias_kernel(const float* __restrict__ bias, float* __restrict__ out) {
    int i = blockIdx.x * blockDim.x + threadIdx.x;
    if (i >= BATCH * 64) return;
    float v = g_r[i] + bias[i & 63];
    out[OUT_REC_OFF + i] = 1.0f / (1.0f + expf(-v));
}

// ---------------- launch ----------------
extern "C" void kernel_launch(void* const* d_in, const int* in_sizes, int n_in,
                              void* d_out, int out_size)
{
    const float* data    = (const float*)d_in[0];
    const float* conv1_w = (const float*)d_in[1];
    const float* conv1_b = (const float*)d_in[2];
    const float* prim_w  = (const float*)d_in[3];
    const float* prim_b  = (const float*)d_in[4];
    const float* W_digit = (const float*)d_in[5];
    const float* dec1_w  = (const float*)d_in[6];
    const float* dec1_b  = (const float*)d_in[7];
    const float* dec2_w  = (const float*)d_in[8];
    const float* dec2_b  = (const float*)d_in[9];
    const float* dec3_w  = (const float*)d_in[10];
    const float* dec3_b  = (const float*)d_in[11];
    float* out = (float*)d_out;

    float *p_bij, *p_s, *p_G, *p_u, *p_WcT, *p_v, *p_r, *p_h0, *p_h1, *p_h2;
    cudaGetSymbolAddress((void**)&p_bij, g_bij);
    cudaGetSymbolAddress((void**)&p_s,   g_s);
    cudaGetSymbolAddress((void**)&p_G,   g_G);
    cudaGetSymbolAddress((void**)&p_u,   g_u);
    cudaGetSymbolAddress((void**)&p_WcT, g_WcT);
    cudaGetSymbolAddress((void**)&p_v,   g_v);
    cudaGetSymbolAddress((void**)&p_r,   g_r);
    cudaGetSymbolAddress((void**)&p_h0,  g_h0);
    cudaGetSymbolAddress((void**)&p_h1,  g_h1);
    cudaGetSymbolAddress((void**)&p_h2,  g_h2);

    static int smem_set = 0;
    if (!smem_set) {
        cudaFuncSetAttribute(conv_tc_kernel,
                             cudaFuncAttributeMaxDynamicSharedMemorySize, CONV_SMEM);
        smem_set = 1;
    }

    wb_split_kernel<<<576, 256>>>(prim_w);                           // 0
    zero_kernel<<<4, 256>>>(p_bij, NR * 2);                          // 1
    zero_kernel<<<512, 256>>>(p_s, BATCH * 32);                      // 2
    zero_kernel<<<512, 256>>>(p_s + BATCH * 32, BATCH * 32);         // 3
    zero_kernel<<<1024, 256>>>(p_G, RI * 64);                        // 4

    conv_tc_kernel<<<BATCH, 512, CONV_SMEM>>>(data, conv1_w, conv1_b, prim_b);  // 5

    for (int it = 0; it < 3; it++) {
        softmax_routes_kernel<<<1, 512>>>();
        build_wct_kernel<<<1024, 256>>>(W_digit);
        if (it > 0) zero_kernel<<<1024, 256>>>(p_s, BATCH * 64);
        tgemm_rm_splitk<<<dim3(1, 64, 8), 256>>>(p_u, p_WcT, p_s, RI, 64, 512);
        squash_v_kernel<<<1024, 256>>>();
        if (it < 2) {
            if (it > 0) zero_kernel<<<1024, 256>>>(p_G, RI * 64);
            tgemm_tr_splitk<<<dim3(1, 64, 8), 256>>>(p_u, p_v, p_G, RI, 64, 512,
                                                     1.0f / (float)BATCH);
            b_update_kernel<<<128, 256>>>(W_digit);
        }
    }

    mask_kernel<<<512, 256>>>(out);
    zero_kernel<<<1024, 256>>>(p_r, BATCH * 64);

    tgemm_rm_bias<<<dim3(8, 64), 256>>>(p_h0, dec1_w, dec1_b, p_h1, 64, 512, 1);
    tgemm_rm_bias<<<dim3(16, 64), 256>>>(p_h1, dec2_w, dec2_b, p_h2, 512, 1024, 1);
    tgemm_rm_splitk<<<dim3(1, 64, 4), 256>>>(p_h2, dec3_w, p_r, 1024, 64, 256);
    sigmoid_bias_kernel<<<1024, 256>>>(dec3_b, out);
}